// round 2
// baseline (speedup 1.0000x reference)
#include <cuda_runtime.h>
#include <math.h>

#define DD   1024
#define BB   16
#define TT   2048
#define NROW (TT*BB)          /* 32768 */
#define BD   (BB*DD)          /* 16384 */
#define NBLK 128              /* scan blocks */
#define JPB  8                /* W_h rows per scan block */

/* ------------- static device scratch (no allocations allowed) ------------- */
__device__ float    g_A[33554432];   /* x@Wx^T + b, [T*B, D], 128MB */
__device__ float    g_scale;         /* 0.99/(sigma+eps) */
__device__ unsigned g_cnt;
__device__ unsigned g_rel;

/* ======================= MT19937 (numpy-exact) =========================== */
struct MT {
    unsigned mt[624];
    int pos;
    __device__ void seed0() {
        unsigned s = 0u;
        for (int i = 0; i < 624; i++) {
            mt[i] = s;
            s = 1812433253u * (s ^ (s >> 30)) + (unsigned)(i + 1);
        }
        pos = 624;
    }
    __device__ unsigned next() {
        if (pos == 624) {
            for (int i = 0; i < 624; i++) {
                unsigned y = (mt[i] & 0x80000000u) | (mt[(i + 1) % 624] & 0x7fffffffu);
                mt[i] = mt[(i + 397) % 624] ^ (y >> 1) ^ ((y & 1u) ? 0x9908b0dfu : 0u);
            }
            pos = 0;
        }
        unsigned y = mt[pos++];
        y ^= y >> 11;
        y ^= (y << 7) & 0x9d2c5680u;
        y ^= (y << 15) & 0xefc60000u;
        y ^= y >> 18;
        return y;
    }
    __device__ double nextDouble() {
        unsigned a = next() >> 5, b = next() >> 6;
        return ((double)a * 67108864.0 + (double)b) / 9007199254740992.0;
    }
};

/* ==================== spectral normalization kernel ====================== */
__device__ __forceinline__ float blk_sum(float x, float* red, int tid) {
    #pragma unroll
    for (int o = 16; o; o >>= 1) x += __shfl_xor_sync(0xffffffffu, x, o);
    if ((tid & 31) == 0) red[tid >> 5] = x;
    __syncthreads();
    if (tid < 32) {
        float r = red[tid];
        #pragma unroll
        for (int o = 16; o; o >>= 1) r += __shfl_xor_sync(0xffffffffu, r, o);
        if (tid == 0) red[0] = r;
    }
    __syncthreads();
    float r = red[0];
    __syncthreads();   /* protect red[] for next call */
    return r;
}

__global__ void spectral_kernel(const float* __restrict__ Wh) {
    __shared__ float u[DD], v[DD], wv[DD];
    __shared__ float red[32];
    int tid = threadIdx.x, lane = tid & 31, wid = tid >> 5;

    if (tid == 0) {   /* numpy RandomState(0).randn(1024), legacy polar gauss */
        MT st; st.seed0();
        bool has_g = false; double gcache = 0.0;
        for (int i = 0; i < DD; i++) {
            double val;
            if (has_g) { val = gcache; has_g = false; }
            else {
                double x1, x2, r2;
                do {
                    x1 = 2.0 * st.nextDouble() - 1.0;
                    x2 = 2.0 * st.nextDouble() - 1.0;
                    r2 = x1 * x1 + x2 * x2;
                } while (r2 >= 1.0 || r2 == 0.0);
                double f = sqrt(-2.0 * log(r2) / r2);
                gcache = f * x1; has_g = true; val = f * x2;
            }
            u[i] = (float)val;
        }
    }
    __syncthreads();

    float nn = sqrtf(blk_sum(u[tid] * u[tid], red, tid));
    u[tid] = u[tid] / nn;
    __syncthreads();

    for (int it = 0; it < 3; it++) {
        /* v = W^T u  (coalesced column access) */
        float s = 0.f;
        #pragma unroll 4
        for (int k = 0; k < DD; k++) s = fmaf(Wh[k * DD + tid], u[k], s);
        v[tid] = s;
        __syncthreads();
        float nv = sqrtf(blk_sum(s * s, red, tid)) + 1e-8f;
        v[tid] = s / nv;
        __syncthreads();
        /* u = W v  (warp-per-row) */
        for (int r = wid; r < DD; r += 32) {
            float p = 0.f;
            #pragma unroll 4
            for (int k = lane; k < DD; k += 32) p = fmaf(Wh[r * DD + k], v[k], p);
            #pragma unroll
            for (int o = 16; o; o >>= 1) p += __shfl_xor_sync(0xffffffffu, p, o);
            if (lane == 0) u[r] = p;
        }
        __syncthreads();
        float nu = sqrtf(blk_sum(u[tid] * u[tid], red, tid)) + 1e-8f;
        u[tid] = u[tid] / nu;
        __syncthreads();
    }

    /* sigma = |u . (W v)| */
    for (int r = wid; r < DD; r += 32) {
        float p = 0.f;
        #pragma unroll 4
        for (int k = lane; k < DD; k += 32) p = fmaf(Wh[r * DD + k], v[k], p);
        #pragma unroll
        for (int o = 16; o; o >>= 1) p += __shfl_xor_sync(0xffffffffu, p, o);
        if (lane == 0) wv[r] = p;
    }
    __syncthreads();
    float sig = blk_sum(u[tid] * wv[tid], red, tid);
    if (tid == 0) g_scale = 0.99f / (fabsf(sig) + 1e-8f);
}

/* ============================ init kernel ================================ */
__global__ void init_kernel(const float* __restrict__ h0, float* __restrict__ out_h) {
    int i = blockIdx.x * blockDim.x + threadIdx.x;
    if (i < BD) out_h[i] = h0[i];
    if (i == 0) { g_cnt = 0u; g_rel = 0u; }
}

/* ============================ tiled SGEMM ================================ */
/* C[M,N] = A[M,K] * B[N,K]^T ; 128x128 tile, 256 thr, 8x8 micro            */
/* MODE 0: g_A[idx] = acc + bias[n]                                         */
/* MODE 1: Cg[idx]  = Hg[idx] * sigmoid(Zg[idx] + acc)                      */
template <int MODE>
__global__ void __launch_bounds__(256, 2)
gemm_kernel(const float* __restrict__ Ag, const float* __restrict__ Bg,
            float* __restrict__ Cg, const float* __restrict__ bias,
            const float* __restrict__ Zg, const float* __restrict__ Hg) {
    __shared__ float SA[16][132];
    __shared__ float SB[16][132];
    int tid = threadIdx.x;
    int m0 = blockIdx.x * 128, n0 = blockIdx.y * 128;
    int lr = tid >> 2, lc = tid & 3;
    int tx = tid & 15, ty = tid >> 4;
    float acc[8][8];
    #pragma unroll
    for (int i = 0; i < 8; i++)
        #pragma unroll
        for (int j = 0; j < 8; j++) acc[i][j] = 0.f;

    for (int k0 = 0; k0 < DD; k0 += 16) {
        float4 a0 = *(const float4*)&Ag[(size_t)(m0 + lr) * DD + k0 + lc * 4];
        float4 a1 = *(const float4*)&Ag[(size_t)(m0 + lr + 64) * DD + k0 + lc * 4];
        float4 b0 = *(const float4*)&Bg[(size_t)(n0 + lr) * DD + k0 + lc * 4];
        float4 b1 = *(const float4*)&Bg[(size_t)(n0 + lr + 64) * DD + k0 + lc * 4];
        __syncthreads();
        SA[lc*4+0][lr] = a0.x; SA[lc*4+1][lr] = a0.y; SA[lc*4+2][lr] = a0.z; SA[lc*4+3][lr] = a0.w;
        SA[lc*4+0][lr+64] = a1.x; SA[lc*4+1][lr+64] = a1.y; SA[lc*4+2][lr+64] = a1.z; SA[lc*4+3][lr+64] = a1.w;
        SB[lc*4+0][lr] = b0.x; SB[lc*4+1][lr] = b0.y; SB[lc*4+2][lr] = b0.z; SB[lc*4+3][lr] = b0.w;
        SB[lc*4+0][lr+64] = b1.x; SB[lc*4+1][lr+64] = b1.y; SB[lc*4+2][lr+64] = b1.z; SB[lc*4+3][lr+64] = b1.w;
        __syncthreads();
        #pragma unroll
        for (int kk = 0; kk < 16; kk++) {
            float4 af0 = *(const float4*)&SA[kk][ty * 8];
            float4 af1 = *(const float4*)&SA[kk][ty * 8 + 4];
            float4 bf0 = *(const float4*)&SB[kk][tx * 8];
            float4 bf1 = *(const float4*)&SB[kk][tx * 8 + 4];
            float ar[8] = {af0.x, af0.y, af0.z, af0.w, af1.x, af1.y, af1.z, af1.w};
            float br[8] = {bf0.x, bf0.y, bf0.z, bf0.w, bf1.x, bf1.y, bf1.z, bf1.w};
            #pragma unroll
            for (int i = 0; i < 8; i++)
                #pragma unroll
                for (int j = 0; j < 8; j++)
                    acc[i][j] = fmaf(ar[i], br[j], acc[i][j]);
        }
    }

    #pragma unroll
    for (int i = 0; i < 8; i++) {
        int m = m0 + ty * 8 + i;
        #pragma unroll
        for (int j = 0; j < 8; j++) {
            int n = n0 + tx * 8 + j;
            size_t idx = (size_t)m * DD + n;
            if (MODE == 0) {
                g_A[idx] = acc[i][j] + __ldg(&bias[n]);
            } else {
                float hv = Hg[idx];
                float gt = 1.0f / (1.0f + expf(-(Zg[idx] + acc[i][j])));
                Cg[idx] = hv * gt;
            }
        }
    }
}

/* ======================= persistent scan kernel ========================== */
/* 128 blocks x 512 thr. warp = batch b; block owns JPB=8 rows of W_h       */
/* (32KB, L1-resident across all steps). h read via __ldcg (L2-coherent).   */
__global__ void __launch_bounds__(512, 1)
scan_kernel(const float* __restrict__ Wh, float* __restrict__ out_h) {
    int tid = threadIdx.x, lane = tid & 31, b = tid >> 5;
    int jbase = blockIdx.x * JPB;
    float s = g_scale;
    const float4* W4 = (const float4*)Wh;

    for (int t = 0; t < TT; t++) {
        const float4* h4 = (const float4*)(out_h + (size_t)t * BD + b * DD);
        float a_val = __ldcg(&g_A[(size_t)t * BD + b * DD + jbase + (lane & 7)]);

        float acc[JPB];
        #pragma unroll
        for (int jj = 0; jj < JPB; jj++) acc[jj] = 0.f;

        #pragma unroll 2
        for (int it = 0; it < 8; it++) {
            float4 h = __ldcg(&h4[it * 32 + lane]);
            #pragma unroll
            for (int jj = 0; jj < JPB; jj++) {
                float4 w = W4[(size_t)(jbase + jj) * (DD / 4) + it * 32 + lane];
                acc[jj] = fmaf(w.x, h.x, acc[jj]);
                acc[jj] = fmaf(w.y, h.y, acc[jj]);
                acc[jj] = fmaf(w.z, h.z, acc[jj]);
                acc[jj] = fmaf(w.w, h.w, acc[jj]);
            }
        }
        #pragma unroll
        for (int jj = 0; jj < JPB; jj++) {
            #pragma unroll
            for (int o = 16; o; o >>= 1)
                acc[jj] += __shfl_xor_sync(0xffffffffu, acc[jj], o);
        }
        float r = acc[0];
        r = (lane == 1) ? acc[1] : r;
        r = (lane == 2) ? acc[2] : r;
        r = (lane == 3) ? acc[3] : r;
        r = (lane == 4) ? acc[4] : r;
        r = (lane == 5) ? acc[5] : r;
        r = (lane == 6) ? acc[6] : r;
        r = (lane == 7) ? acc[7] : r;
        if (lane < 8) {
            float hv = tanhf(fmaf(s, r, a_val));
            out_h[(size_t)(t + 1) * BD + b * DD + jbase + lane] = hv;
        }

        /* grid barrier: monotonic counter + release epoch */
        __syncthreads();
        if (tid == 0) {
            __threadfence();
            unsigned prev = atomicAdd(&g_cnt, 1u);
            unsigned target = (unsigned)(t + 1) * NBLK;
            if (prev + 1u == target) {
                atomicExch(&g_rel, (unsigned)(t + 1));
            } else {
                volatile unsigned* rel = &g_rel;
                while (*rel < (unsigned)(t + 1)) { }
            }
            __threadfence();
        }
        __syncthreads();
    }
}

/* ============================== launcher ================================= */
extern "C" void kernel_launch(void* const* d_in, const int* in_sizes, int n_in,
                              void* d_out, int out_size) {
    const float* x    = (const float*)d_in[0];
    const float* z    = (const float*)d_in[1];
    const float* h0   = (const float*)d_in[2];
    const float* Wx   = (const float*)d_in[3];
    const float* Wh   = (const float*)d_in[4];
    const float* Wg   = (const float*)d_in[5];
    const float* bias = (const float*)d_in[6];

    float* out   = (float*)d_out;
    float* outs  = out;                          /* [T, B, D]   */
    float* out_h = out + (size_t)NROW * DD;      /* [T+1, B, D] */
    const float* hs = out_h + BD;                /* h[1..T] rows = (t*B+b) */

    spectral_kernel<<<1, 1024>>>(Wh);
    init_kernel<<<16, 1024>>>(h0, out_h);
    gemm_kernel<0><<<dim3(NROW / 128, DD / 128), 256>>>(x, Wx, nullptr, bias, nullptr, nullptr);
    scan_kernel<<<NBLK, 512>>>(Wh, out_h);
    gemm_kernel<1><<<dim3(NROW / 128, DD / 128), 256>>>(hs, Wg, outs, nullptr, z, hs);
}

// round 3
// speedup vs baseline: 1.4114x; 1.4114x over previous
#include <cuda_runtime.h>
#include <math.h>

#define DD   1024
#define BB   16
#define TT   2048
#define NROW (TT*BB)          /* 32768 */
#define BD   (BB*DD)          /* 16384 */
#define NBLK 128              /* scan blocks */

/* ------------- static device scratch (no allocations allowed) ------------- */
__device__ float    g_A[33554432];   /* x@Wx^T + b, [T*B, D], 128MB */
__device__ float    g_u[DD];
__device__ float    g_v[DD];
__device__ float    g_part[16][DD];
__device__ float    g_scale;         /* 0.99/(sigma+eps) */
__device__ unsigned g_cnt;
__device__ unsigned g_rel;

/* ====================== small PTX helpers ================================ */
__device__ __forceinline__ void ffma2(unsigned long long& acc,
                                      unsigned long long a, unsigned long long b) {
    asm("fma.rn.f32x2 %0, %1, %2, %0;" : "+l"(acc) : "l"(a), "l"(b));
}
__device__ __forceinline__ void ld_v2u64_cg(unsigned long long& lo, unsigned long long& hi,
                                            const void* p) {
    asm volatile("ld.global.cg.v2.u64 {%0,%1}, [%2];" : "=l"(lo), "=l"(hi) : "l"(p));
}
__device__ __forceinline__ void ld_v2u64_nc(unsigned long long& lo, unsigned long long& hi,
                                            const void* p) {
    asm volatile("ld.global.nc.v2.u64 {%0,%1}, [%2];" : "=l"(lo), "=l"(hi) : "l"(p));
}
__device__ __forceinline__ unsigned f2tf(float f) {
    unsigned r;
    asm("cvt.rna.tf32.f32 %0, %1;" : "=r"(r) : "f"(f));
    return r;
}
__device__ __forceinline__ void mma_tf32(float* c, const unsigned* a, unsigned b0, unsigned b1) {
    asm volatile(
        "mma.sync.aligned.m16n8k8.row.col.f32.tf32.tf32.f32 "
        "{%0,%1,%2,%3},{%4,%5,%6,%7},{%8,%9},{%0,%1,%2,%3};"
        : "+f"(c[0]), "+f"(c[1]), "+f"(c[2]), "+f"(c[3])
        : "r"(a[0]), "r"(a[1]), "r"(a[2]), "r"(a[3]), "r"(b0), "r"(b1));
}

/* ===================== block-wide sum reduce ============================= */
__device__ __forceinline__ float blk_sum(float x, float* red, int tid) {
    #pragma unroll
    for (int o = 16; o; o >>= 1) x += __shfl_xor_sync(0xffffffffu, x, o);
    if ((tid & 31) == 0) red[tid >> 5] = x;
    __syncthreads();
    if (tid < 32) {
        float r = (tid < (int)(blockDim.x >> 5)) ? red[tid] : 0.f;
        #pragma unroll
        for (int o = 16; o; o >>= 1) r += __shfl_xor_sync(0xffffffffu, r, o);
        if (tid == 0) red[0] = r;
    }
    __syncthreads();
    float r = red[0];
    __syncthreads();
    return r;
}

/* ================= spectral normalization pipeline ======================= */
struct P512 { float v[512]; };

__global__ void write_u_kernel(P512 a, int off) {
    g_u[off + threadIdx.x] = a.v[threadIdx.x];
}

__global__ void norm_u_kernel() {   /* u /= ||u||  (no eps, matches ref init) */
    __shared__ float red[32];
    int tid = threadIdx.x;
    float x = g_u[tid];
    float n = sqrtf(blk_sum(x * x, red, tid));
    g_u[tid] = x / n;
}

/* v_part[bk][j] = sum_{k in slab} W[k][j] * u[k]   (grid 16, block 1024) */
__global__ void matvecT_kernel(const float* __restrict__ Wh) {
    __shared__ float us[64];
    int j = threadIdx.x, k0 = blockIdx.x * 64;
    if (j < 64) us[j] = g_u[k0 + j];
    __syncthreads();
    float s = 0.f;
    #pragma unroll 8
    for (int k = 0; k < 64; k++) s = fmaf(Wh[(size_t)(k0 + k) * DD + j], us[k], s);
    g_part[blockIdx.x][j] = s;
}

__global__ void vnorm_kernel() {    /* v = reduce(part); v /= (||v||+eps) */
    __shared__ float red[32];
    int tid = threadIdx.x;
    float v = 0.f;
    #pragma unroll
    for (int i = 0; i < 16; i++) v += g_part[i][tid];
    float n = sqrtf(blk_sum(v * v, red, tid)) + 1e-8f;
    g_v[tid] = v / n;
}

/* u_raw[r] = W[r,:] . v    (grid 32, block 256, warp handles 4 rows) */
__global__ void matvec_kernel(const float* __restrict__ Wh) {
    int lane = threadIdx.x & 31, wid = threadIdx.x >> 5;
    const float4* W4 = (const float4*)Wh;
    const float4* v4 = (const float4*)g_v;
    #pragma unroll
    for (int rr = 0; rr < 4; rr++) {
        int r = blockIdx.x * 32 + wid * 4 + rr;
        float p = 0.f;
        #pragma unroll
        for (int it = 0; it < 8; it++) {
            float4 w = W4[(size_t)r * 256 + it * 32 + lane];
            float4 v = v4[it * 32 + lane];
            p = fmaf(w.x, v.x, p); p = fmaf(w.y, v.y, p);
            p = fmaf(w.z, v.z, p); p = fmaf(w.w, v.w, p);
        }
        #pragma unroll
        for (int o = 16; o; o >>= 1) p += __shfl_xor_sync(0xffffffffu, p, o);
        if (lane == 0) g_u[r] = p;
    }
}

__global__ void unorm_kernel(int final_it) {  /* u /= (||u||+eps); maybe sigma */
    __shared__ float red[32];
    int tid = threadIdx.x;
    float x = g_u[tid];
    float n = sqrtf(blk_sum(x * x, red, tid));
    g_u[tid] = x / (n + 1e-8f);
    if (final_it && tid == 0) {
        /* sigma = u.(Wv) = ||Wv||^2/(||Wv||+eps) since u = Wv/(||Wv||+eps) */
        float sig = n * n / (n + 1e-8f);
        g_scale = 0.99f / (sig + 1e-8f);
    }
}

/* ============================ init kernel ================================ */
__global__ void init_kernel(const float* __restrict__ h0, float* __restrict__ out_h) {
    int i = blockIdx.x * blockDim.x + threadIdx.x;
    if (i < BD) out_h[i] = h0[i];
    if (i == 0) { g_cnt = 0u; g_rel = 0u; }
}

/* ===================== tf32 tensor-core GEMM ============================= */
/* C[M,N] = A[M,K]*B[N,K]^T, M-tile 128, N-tile 128, 8 warps (4Mx2N),       */
/* warp tile 32x64, mma.m16n8k8.tf32, fp32 accum.                           */
/* MODE 0: g_A = acc + bias[n]    MODE 1: Cg = Hg * sigmoid(Zg + acc)       */
template <int MODE>
__global__ void __launch_bounds__(256, 2)
gemm_kernel(const float* __restrict__ Ag, const float* __restrict__ Bg,
            float* __restrict__ Cg, const float* __restrict__ bias,
            const float* __restrict__ Zg, const float* __restrict__ Hg) {
    __shared__ unsigned As[128][36];
    __shared__ unsigned Bs[128][36];
    int tid = threadIdx.x, lane = tid & 31, wid = tid >> 5;
    int wm = wid >> 1, wn = wid & 1;
    int m0 = blockIdx.x * 128, n0 = blockIdx.y * 128;

    float acc[2][8][4];
    #pragma unroll
    for (int mt = 0; mt < 2; mt++)
        #pragma unroll
        for (int nt = 0; nt < 8; nt++)
            #pragma unroll
            for (int i = 0; i < 4; i++) acc[mt][nt][i] = 0.f;

    float4 abuf[4], bbuf[4];
    /* prefetch chunk 0 */
    #pragma unroll
    for (int f = 0; f < 4; f++) {
        int q = f * 256 + tid, row = q >> 3, c4 = q & 7;
        abuf[f] = *(const float4*)&Ag[(size_t)(m0 + row) * DD + c4 * 4];
        bbuf[f] = *(const float4*)&Bg[(size_t)(n0 + row) * DD + c4 * 4];
    }

    for (int c = 0; c < 32; c++) {
        /* store current chunk to smem with tf32 rounding */
        #pragma unroll
        for (int f = 0; f < 4; f++) {
            int q = f * 256 + tid, row = q >> 3, cc = (q & 7) * 4;
            *(uint4*)&As[row][cc] = make_uint4(f2tf(abuf[f].x), f2tf(abuf[f].y),
                                               f2tf(abuf[f].z), f2tf(abuf[f].w));
            *(uint4*)&Bs[row][cc] = make_uint4(f2tf(bbuf[f].x), f2tf(bbuf[f].y),
                                               f2tf(bbuf[f].z), f2tf(bbuf[f].w));
        }
        __syncthreads();
        if (c < 31) {
            int k0 = (c + 1) * 32;
            #pragma unroll
            for (int f = 0; f < 4; f++) {
                int q = f * 256 + tid, row = q >> 3, c4 = q & 7;
                abuf[f] = *(const float4*)&Ag[(size_t)(m0 + row) * DD + k0 + c4 * 4];
                bbuf[f] = *(const float4*)&Bg[(size_t)(n0 + row) * DD + k0 + c4 * 4];
            }
        }
        #pragma unroll
        for (int kk = 0; kk < 4; kk++) {
            unsigned a[2][4];
            int ar = wm * 32 + (lane >> 2);
            int kc = kk * 8 + (lane & 3);
            #pragma unroll
            for (int mt = 0; mt < 2; mt++) {
                int r = ar + mt * 16;
                a[mt][0] = As[r][kc];
                a[mt][1] = As[r + 8][kc];
                a[mt][2] = As[r][kc + 4];
                a[mt][3] = As[r + 8][kc + 4];
            }
            #pragma unroll
            for (int nt = 0; nt < 8; nt++) {
                int nc = wn * 64 + nt * 8 + (lane >> 2);
                unsigned b0 = Bs[nc][kc];
                unsigned b1 = Bs[nc][kc + 4];
                mma_tf32(acc[0][nt], a[0], b0, b1);
                mma_tf32(acc[1][nt], a[1], b0, b1);
            }
        }
        __syncthreads();
    }

    /* epilogue */
    #pragma unroll
    for (int mt = 0; mt < 2; mt++) {
        int r = m0 + wm * 32 + mt * 16 + (lane >> 2);
        #pragma unroll
        for (int nt = 0; nt < 8; nt++) {
            int cc = n0 + wn * 64 + nt * 8 + (lane & 3) * 2;
            #pragma unroll
            for (int half = 0; half < 2; half++) {
                int rr = r + half * 8;
                size_t i0 = (size_t)rr * DD + cc;
                float v0 = acc[mt][nt][half * 2 + 0];
                float v1 = acc[mt][nt][half * 2 + 1];
                if (MODE == 0) {
                    g_A[i0]     = v0 + __ldg(&bias[cc]);
                    g_A[i0 + 1] = v1 + __ldg(&bias[cc + 1]);
                } else {
                    float h0v = Hg[i0], h1v = Hg[i0 + 1];
                    float g0 = 1.0f / (1.0f + expf(-(Zg[i0] + v0)));
                    float g1 = 1.0f / (1.0f + expf(-(Zg[i0 + 1] + v1)));
                    Cg[i0]     = h0v * g0;
                    Cg[i0 + 1] = h1v * g1;
                }
            }
        }
    }
}

/* ======================= persistent scan kernel ========================== */
/* 128 blocks x 512 thr (16 warps). Block owns 8 rows of W_h.               */
/* Warp (p = wid>>2, g = wid&3): rows {jbase+2p, jbase+2p+1} x batches      */
/* {4g..4g+3}. W_h held entirely in REGISTERS (64 regs/lane). Inner loop    */
/* uses packed fma.rn.f32x2 (FFMA2) to halve fma-pipe issue.                */
__global__ void __launch_bounds__(512, 1)
scan_kernel(const float* __restrict__ Wh, float* __restrict__ out_h) {
    int tid = threadIdx.x, lane = tid & 31, wid = tid >> 5;
    int pair = wid >> 2, bg = wid & 3;
    int r0 = blockIdx.x * 8 + pair * 2;        /* rows r0, r0+1 */

    /* preload W rows into registers: w01 = k-lane pair (x,y), w23 = (z,w) */
    unsigned long long w01[2][8], w23[2][8];
    #pragma unroll
    for (int rr = 0; rr < 2; rr++)
        #pragma unroll
        for (int it = 0; it < 8; it++)
            ld_v2u64_nc(w01[rr][it], w23[rr][it],
                        Wh + (size_t)(r0 + rr) * DD + it * 128 + lane * 4);

    float s = g_scale;
    int l8 = lane & 7;
    int out_b   = bg * 4 + (l8 & 3);
    int out_row = r0 + (l8 >> 2);

    for (int t = 0; t < TT; t++) {
        const float* hbase = out_h + (size_t)t * BD;
        float a_val = __ldcg(&g_A[(size_t)t * BD + (size_t)out_b * DD + out_row]);

        unsigned long long acc[2][4];
        #pragma unroll
        for (int rr = 0; rr < 2; rr++)
            #pragma unroll
            for (int b2 = 0; b2 < 4; b2++) acc[rr][b2] = 0ULL;

        #pragma unroll 2
        for (int it = 0; it < 8; it++) {
            unsigned long long ha[4], hb[4];
            #pragma unroll
            for (int b2 = 0; b2 < 4; b2++)
                ld_v2u64_cg(ha[b2], hb[b2],
                            hbase + (size_t)(bg * 4 + b2) * DD + it * 128 + lane * 4);
            #pragma unroll
            for (int b2 = 0; b2 < 4; b2++) {
                ffma2(acc[0][b2], w01[0][it], ha[b2]);
                ffma2(acc[0][b2], w23[0][it], hb[b2]);
                ffma2(acc[1][b2], w01[1][it], ha[b2]);
                ffma2(acc[1][b2], w23[1][it], hb[b2]);
            }
        }

        /* reduce: unpack packed pairs, butterfly each of 8 values */
        float v[8];
        #pragma unroll
        for (int rr = 0; rr < 2; rr++)
            #pragma unroll
            for (int b2 = 0; b2 < 4; b2++) {
                float lo, hi;
                asm("mov.b64 {%0,%1}, %2;" : "=f"(lo), "=f"(hi) : "l"(acc[rr][b2]));
                float x = lo + hi;
                #pragma unroll
                for (int o = 16; o; o >>= 1) x += __shfl_xor_sync(0xffffffffu, x, o);
                v[rr * 4 + b2] = x;
            }
        float r = v[0];
        r = (l8 == 1) ? v[1] : r;
        r = (l8 == 2) ? v[2] : r;
        r = (l8 == 3) ? v[3] : r;
        r = (l8 == 4) ? v[4] : r;
        r = (l8 == 5) ? v[5] : r;
        r = (l8 == 6) ? v[6] : r;
        r = (l8 == 7) ? v[7] : r;
        if (lane < 8) {
            float hv = tanhf(fmaf(s, r, a_val));
            out_h[(size_t)(t + 1) * BD + (size_t)out_b * DD + out_row] = hv;
        }

        /* grid barrier: monotonic counter + release epoch */
        __syncthreads();
        if (tid == 0) {
            __threadfence();
            unsigned prev = atomicAdd(&g_cnt, 1u);
            unsigned target = (unsigned)(t + 1) * NBLK;
            if (prev + 1u == target) {
                atomicExch(&g_rel, (unsigned)(t + 1));
            } else {
                volatile unsigned* rel = &g_rel;
                while (*rel < (unsigned)(t + 1)) { }
            }
            __threadfence();
        }
        __syncthreads();
    }
}

/* ================== host-side numpy-exact randn(1024) ==================== */
static void host_randn1024(float* out) {
    /* MT19937 seeded with 0, numpy legacy polar gauss */
    static unsigned mt[624];
    int pos;
    {
        unsigned s = 0u;
        for (int i = 0; i < 624; i++) {
            mt[i] = s;
            s = 1812433253u * (s ^ (s >> 30)) + (unsigned)(i + 1);
        }
        pos = 624;
    }
    auto next = [&]() -> unsigned {
        if (pos == 624) {
            for (int i = 0; i < 624; i++) {
                unsigned y = (mt[i] & 0x80000000u) | (mt[(i + 1) % 624] & 0x7fffffffu);
                mt[i] = mt[(i + 397) % 624] ^ (y >> 1) ^ ((y & 1u) ? 0x9908b0dfu : 0u);
            }
            pos = 0;
        }
        unsigned y = mt[pos++];
        y ^= y >> 11;
        y ^= (y << 7) & 0x9d2c5680u;
        y ^= (y << 15) & 0xefc60000u;
        y ^= y >> 18;
        return y;
    };
    auto nextDouble = [&]() -> double {
        unsigned a = next() >> 5, b = next() >> 6;
        return ((double)a * 67108864.0 + (double)b) / 9007199254740992.0;
    };
    bool has_g = false;
    double gcache = 0.0;
    for (int i = 0; i < DD; i++) {
        double val;
        if (has_g) { val = gcache; has_g = false; }
        else {
            double x1, x2, r2;
            do {
                x1 = 2.0 * nextDouble() - 1.0;
                x2 = 2.0 * nextDouble() - 1.0;
                r2 = x1 * x1 + x2 * x2;
            } while (r2 >= 1.0 || r2 == 0.0);
            double f = sqrt(-2.0 * log(r2) / r2);
            gcache = f * x1; has_g = true; val = f * x2;
        }
        out[i] = (float)val;
    }
}

/* ============================== launcher ================================= */
extern "C" void kernel_launch(void* const* d_in, const int* in_sizes, int n_in,
                              void* d_out, int out_size) {
    const float* x    = (const float*)d_in[0];
    const float* z    = (const float*)d_in[1];
    const float* h0   = (const float*)d_in[2];
    const float* Wx   = (const float*)d_in[3];
    const float* Wh   = (const float*)d_in[4];
    const float* Wg   = (const float*)d_in[5];
    const float* bias = (const float*)d_in[6];

    float* out   = (float*)d_out;
    float* outs  = out;                          /* [T, B, D]   */
    float* out_h = out + (size_t)NROW * DD;      /* [T+1, B, D] */
    const float* hs = out_h + BD;                /* h[1..T], row = t*B+b */

    /* spectral normalization: host randn -> param-struct upload -> power it */
    static float u_host[DD];
    host_randn1024(u_host);
    P512 p0, p1;
    for (int i = 0; i < 512; i++) { p0.v[i] = u_host[i]; p1.v[i] = u_host[512 + i]; }
    write_u_kernel<<<1, 512>>>(p0, 0);
    write_u_kernel<<<1, 512>>>(p1, 512);
    norm_u_kernel<<<1, 1024>>>();
    for (int it = 0; it < 3; it++) {
        matvecT_kernel<<<16, 1024>>>(Wh);
        vnorm_kernel<<<1, 1024>>>();
        matvec_kernel<<<32, 256>>>(Wh);
        unorm_kernel<<<1, 1024>>>(it == 2 ? 1 : 0);
    }

    init_kernel<<<16, 1024>>>(h0, out_h);
    gemm_kernel<0><<<dim3(NROW / 128, DD / 128), 256>>>(x, Wx, nullptr, bias, nullptr, nullptr);
    scan_kernel<<<NBLK, 512>>>(Wh, out_h);
    gemm_kernel<1><<<dim3(NROW / 128, DD / 128), 256>>>(hs, Wg, outs, nullptr, z, hs);
}

// round 4
// speedup vs baseline: 1.6984x; 1.2033x over previous
#include <cuda_runtime.h>
#include <math.h>

#define DD   1024
#define BB   16
#define TT   2048
#define NROW (TT*BB)          /* 32768 */
#define BD   (BB*DD)          /* 16384 */
#define SNB  128              /* scan blocks total */
#define GRP  4                /* independent batch groups */
#define BPG  32               /* blocks per group */

/* ------------- static device scratch (no allocations allowed) ------------- */
__device__ float    g_A[33554432];   /* x@Wx^T + b, [T*B, D], 128MB */
__device__ float    g_scale;         /* 0.99/(sigma+eps) */
__device__ unsigned g_cnt4[GRP * 32];
__device__ unsigned g_rel4[GRP * 32];

/* ====================== small PTX helpers ================================ */
__device__ __forceinline__ void ffma2(unsigned long long& acc,
                                      unsigned long long a, unsigned long long b) {
    asm("fma.rn.f32x2 %0, %1, %2, %0;" : "+l"(acc) : "l"(a), "l"(b));
}
__device__ __forceinline__ void ld_v2u64_ca(unsigned long long& lo, unsigned long long& hi,
                                            const void* p) {
    asm volatile("ld.global.v2.u64 {%0,%1}, [%2];" : "=l"(lo), "=l"(hi) : "l"(p));
}
__device__ __forceinline__ void ld_v2u64_nc(unsigned long long& lo, unsigned long long& hi,
                                            const void* p) {
    asm volatile("ld.global.nc.v2.u64 {%0,%1}, [%2];" : "=l"(lo), "=l"(hi) : "l"(p));
}
__device__ __forceinline__ unsigned f2tf(float f) {
    unsigned r;
    asm("cvt.rna.tf32.f32 %0, %1;" : "=r"(r) : "f"(f));
    return r;
}
__device__ __forceinline__ void mma_tf32(float* c, const unsigned* a, unsigned b0, unsigned b1) {
    asm volatile(
        "mma.sync.aligned.m16n8k8.row.col.f32.tf32.tf32.f32 "
        "{%0,%1,%2,%3},{%4,%5,%6,%7},{%8,%9},{%0,%1,%2,%3};"
        : "+f"(c[0]), "+f"(c[1]), "+f"(c[2]), "+f"(c[3])
        : "r"(a[0]), "r"(a[1]), "r"(a[2]), "r"(a[3]), "r"(b0), "r"(b1));
}

/* ===================== block-wide sum reduce ============================= */
__device__ __forceinline__ float blk_sum(float x, float* red, int tid) {
    #pragma unroll
    for (int o = 16; o; o >>= 1) x += __shfl_xor_sync(0xffffffffu, x, o);
    if ((tid & 31) == 0) red[tid >> 5] = x;
    __syncthreads();
    if (tid < 32) {
        float r = (tid < (int)(blockDim.x >> 5)) ? red[tid] : 0.f;
        #pragma unroll
        for (int o = 16; o; o >>= 1) r += __shfl_xor_sync(0xffffffffu, r, o);
        if (tid == 0) red[0] = r;
    }
    __syncthreads();
    float r = red[0];
    __syncthreads();
    return r;
}

/* ==================== fused spectral normalization ======================= */
struct P1024 { float v[1024]; };

__global__ void spectral_kernel(const float* __restrict__ Wh, P1024 u0) {
    __shared__ float u[DD], v[DD];
    __shared__ float red[32];
    int tid = threadIdx.x, lane = tid & 31, wid = tid >> 5;

    float x = u0.v[tid];
    float n0 = sqrtf(blk_sum(x * x, red, tid));   /* no eps: matches ref init */
    u[tid] = x / n0;
    __syncthreads();

    for (int it = 0; it < 3; it++) {
        /* v_raw = W^T u (coalesced column access) */
        float s = 0.f;
        #pragma unroll 4
        for (int k = 0; k < DD; k++) s = fmaf(__ldg(&Wh[(size_t)k * DD + tid]), u[k], s);
        float nv = sqrtf(blk_sum(s * s, red, tid)) + 1e-8f;
        v[tid] = s / nv;
        __syncthreads();

        /* u_raw = W v (warp-per-row) */
        for (int r = wid; r < DD; r += 32) {
            float p = 0.f;
            const float4* W4 = (const float4*)(Wh + (size_t)r * DD);
            const float4* v4 = (const float4*)v;
            #pragma unroll
            for (int i2 = 0; i2 < 8; i2++) {
                float4 w = __ldg(&W4[i2 * 32 + lane]);
                float4 vv = v4[i2 * 32 + lane];
                p = fmaf(w.x, vv.x, p); p = fmaf(w.y, vv.y, p);
                p = fmaf(w.z, vv.z, p); p = fmaf(w.w, vv.w, p);
            }
            #pragma unroll
            for (int o = 16; o; o >>= 1) p += __shfl_xor_sync(0xffffffffu, p, o);
            if (lane == 0) u[r] = p;
        }
        __syncthreads();
        float nu = sqrtf(blk_sum(u[tid] * u[tid], red, tid));
        if (it == 2 && tid == 0) {
            /* sigma = u.(Wv) = ||Wv||^2/(||Wv||+eps) since u = Wv/(||Wv||+eps) */
            float sig = nu * nu / (nu + 1e-8f);
            g_scale = 0.99f / (sig + 1e-8f);
        }
        u[tid] = u[tid] / (nu + 1e-8f);
        __syncthreads();
    }
}

/* ============================ init / reset =============================== */
__global__ void init_kernel(const float* __restrict__ h0, float* __restrict__ out_h) {
    int i = blockIdx.x * blockDim.x + threadIdx.x;
    if (i < BD) out_h[i] = h0[i];
    if (i < GRP) { g_cnt4[i * 32] = 0u; g_rel4[i * 32] = 0u; }
}
__global__ void reset_kernel() {
    int i = threadIdx.x;
    if (i < GRP) { g_cnt4[i * 32] = 0u; g_rel4[i * 32] = 0u; }
}

/* ===================== tf32 tensor-core GEMM ============================= */
/* C[M,N] = A[M,K]*B[N,K]^T, 128x128 tile, 8 warps, mma.m16n8k8.tf32.       */
/* MODE 0: g_A = acc + bias[n]    MODE 1: Cg = Hg * sigmoid(Zg + acc)       */
template <int MODE>
__global__ void __launch_bounds__(256, 2)
gemm_kernel(const float* __restrict__ Ag, const float* __restrict__ Bg,
            float* __restrict__ Cg, const float* __restrict__ bias,
            const float* __restrict__ Zg, const float* __restrict__ Hg,
            int m_off) {
    __shared__ unsigned As[128][36];
    __shared__ unsigned Bs[128][36];
    int tid = threadIdx.x, lane = tid & 31, wid = tid >> 5;
    int wm = wid >> 1, wn = wid & 1;
    int m0 = m_off + blockIdx.x * 128, n0 = blockIdx.y * 128;

    float acc[2][8][4];
    #pragma unroll
    for (int mt = 0; mt < 2; mt++)
        #pragma unroll
        for (int nt = 0; nt < 8; nt++)
            #pragma unroll
            for (int i = 0; i < 4; i++) acc[mt][nt][i] = 0.f;

    float4 abuf[4], bbuf[4];
    #pragma unroll
    for (int f = 0; f < 4; f++) {
        int q = f * 256 + tid, row = q >> 3, c4 = q & 7;
        abuf[f] = *(const float4*)&Ag[(size_t)(m0 + row) * DD + c4 * 4];
        bbuf[f] = *(const float4*)&Bg[(size_t)(n0 + row) * DD + c4 * 4];
    }

    for (int c = 0; c < 32; c++) {
        #pragma unroll
        for (int f = 0; f < 4; f++) {
            int q = f * 256 + tid, row = q >> 3, cc = (q & 7) * 4;
            *(uint4*)&As[row][cc] = make_uint4(f2tf(abuf[f].x), f2tf(abuf[f].y),
                                               f2tf(abuf[f].z), f2tf(abuf[f].w));
            *(uint4*)&Bs[row][cc] = make_uint4(f2tf(bbuf[f].x), f2tf(bbuf[f].y),
                                               f2tf(bbuf[f].z), f2tf(bbuf[f].w));
        }
        __syncthreads();
        if (c < 31) {
            int k0 = (c + 1) * 32;
            #pragma unroll
            for (int f = 0; f < 4; f++) {
                int q = f * 256 + tid, row = q >> 3, c4 = q & 7;
                abuf[f] = *(const float4*)&Ag[(size_t)(m0 + row) * DD + k0 + c4 * 4];
                bbuf[f] = *(const float4*)&Bg[(size_t)(n0 + row) * DD + k0 + c4 * 4];
            }
        }
        #pragma unroll
        for (int kk = 0; kk < 4; kk++) {
            unsigned a[2][4];
            int ar = wm * 32 + (lane >> 2);
            int kc = kk * 8 + (lane & 3);
            #pragma unroll
            for (int mt = 0; mt < 2; mt++) {
                int r = ar + mt * 16;
                a[mt][0] = As[r][kc];
                a[mt][1] = As[r + 8][kc];
                a[mt][2] = As[r][kc + 4];
                a[mt][3] = As[r + 8][kc + 4];
            }
            #pragma unroll
            for (int nt = 0; nt < 8; nt++) {
                int nc = wn * 64 + nt * 8 + (lane >> 2);
                unsigned b0 = Bs[nc][kc];
                unsigned b1 = Bs[nc][kc + 4];
                mma_tf32(acc[0][nt], a[0], b0, b1);
                mma_tf32(acc[1][nt], a[1], b0, b1);
            }
        }
        __syncthreads();
    }

    #pragma unroll
    for (int mt = 0; mt < 2; mt++) {
        int r = m0 + wm * 32 + mt * 16 + (lane >> 2);
        #pragma unroll
        for (int nt = 0; nt < 8; nt++) {
            int cc = n0 + wn * 64 + nt * 8 + (lane & 3) * 2;
            #pragma unroll
            for (int half = 0; half < 2; half++) {
                int rr = r + half * 8;
                size_t i0 = (size_t)rr * DD + cc;
                float v0 = acc[mt][nt][half * 2 + 0];
                float v1 = acc[mt][nt][half * 2 + 1];
                if (MODE == 0) {
                    g_A[i0]     = v0 + __ldg(&bias[cc]);
                    g_A[i0 + 1] = v1 + __ldg(&bias[cc + 1]);
                } else {
                    float h0v = Hg[i0], h1v = Hg[i0 + 1];
                    float g0 = 1.0f / (1.0f + __expf(-(Zg[i0] + v0)));
                    float g1 = 1.0f / (1.0f + __expf(-(Zg[i0 + 1] + v1)));
                    Cg[i0]     = h0v * g0;
                    Cg[i0 + 1] = h1v * g1;
                }
            }
        }
    }
}

/* ======================= persistent scan kernel ========================== */
/* 128 blocks = 4 groups x 32. Group g handles batches 4g..4g+3 only.       */
/* Block: 32 rows x 4 batches; warp (8/block): 4 rows x 4 batches.          */
/* W_h in registers (128/lane). h via cached loads (L1 dedups the 8-warp    */
/* reuse; safe: out_h[t] region first touched at step t). Per-group 32-wide */
/* barrier; g_A prefetched one step ahead.                                  */
__global__ void __launch_bounds__(256, 1)
scan_kernel(const float* __restrict__ Wh, float* __restrict__ out_h) {
    int tid = threadIdx.x, lane = tid & 31, wid = tid >> 5;
    int gid = blockIdx.x >> 5;         /* group 0..3 */
    int bin = blockIdx.x & 31;         /* block within group */
    int r0 = bin * 32 + wid * 4;       /* this warp's 4 rows */
    int gb = gid * 4;                  /* batch base */

    /* preload W rows into registers: w01 = (k,k+1), w23 = (k+2,k+3) */
    unsigned long long w01[4][8], w23[4][8];
    #pragma unroll
    for (int rr = 0; rr < 4; rr++)
        #pragma unroll
        for (int it = 0; it < 8; it++)
            ld_v2u64_nc(w01[rr][it], w23[rr][it],
                        Wh + (size_t)(r0 + rr) * DD + it * 128 + lane * 4);

    float s = g_scale;
    int l16 = lane & 15;
    int out_b   = gb + (l16 & 3);
    int out_row = r0 + (l16 >> 2);
    unsigned* cnt = &g_cnt4[gid * 32];
    volatile unsigned* rel = (volatile unsigned*)&g_rel4[gid * 32];

    float a_val = __ldcg(&g_A[(size_t)out_b * DD + out_row]);   /* t = 0 */

    for (int t = 0; t < TT; t++) {
        const float* hbase = out_h + (size_t)t * BD;

        unsigned long long acc[4][4];
        #pragma unroll
        for (int rr = 0; rr < 4; rr++)
            #pragma unroll
            for (int b2 = 0; b2 < 4; b2++) acc[rr][b2] = 0ULL;

        #pragma unroll
        for (int it = 0; it < 8; it++) {
            unsigned long long ha[4], hb[4];
            #pragma unroll
            for (int b2 = 0; b2 < 4; b2++)
                ld_v2u64_ca(ha[b2], hb[b2],
                            hbase + (size_t)(gb + b2) * DD + it * 128 + lane * 4);
            #pragma unroll
            for (int rr = 0; rr < 4; rr++)
                #pragma unroll
                for (int b2 = 0; b2 < 4; b2++) {
                    ffma2(acc[rr][b2], w01[rr][it], ha[b2]);
                    ffma2(acc[rr][b2], w23[rr][it], hb[b2]);
                }
        }

        /* prefetch next step's additive term (independent of h) */
        float a_next = 0.f;
        if (t + 1 < TT)
            a_next = __ldcg(&g_A[(size_t)(t + 1) * BD + (size_t)out_b * DD + out_row]);

        /* reduce 16 accumulators */
        float v[16];
        #pragma unroll
        for (int rr = 0; rr < 4; rr++)
            #pragma unroll
            for (int b2 = 0; b2 < 4; b2++) {
                float lo, hi;
                asm("mov.b64 {%0,%1}, %2;" : "=f"(lo), "=f"(hi) : "l"(acc[rr][b2]));
                float x = lo + hi;
                #pragma unroll
                for (int o = 16; o; o >>= 1) x += __shfl_xor_sync(0xffffffffu, x, o);
                v[rr * 4 + b2] = x;
            }
        float r = v[0];
        #pragma unroll
        for (int j = 1; j < 16; j++) r = (l16 == j) ? v[j] : r;

        if (lane < 16) {
            float hv = tanhf(fmaf(s, r, a_val));
            out_h[(size_t)(t + 1) * BD + (size_t)out_b * DD + out_row] = hv;
        }

        /* group barrier (32 blocks): counter + release epoch */
        __threadfence();
        __syncthreads();
        if (tid == 0) {
            unsigned prev = atomicAdd(cnt, 1u);
            unsigned target = (unsigned)(t + 1) * (unsigned)BPG;
            if (prev + 1u == target) {
                atomicExch((unsigned*)rel, (unsigned)(t + 1));
            } else {
                while (*rel < (unsigned)(t + 1)) { }
            }
            __threadfence();
        }
        __syncthreads();
        a_val = a_next;
    }
}

/* ================== host-side numpy-exact randn(1024) ==================== */
static void host_randn1024(float* out) {
    static unsigned mt[624];
    int pos;
    {
        unsigned s = 0u;
        for (int i = 0; i < 624; i++) {
            mt[i] = s;
            s = 1812433253u * (s ^ (s >> 30)) + (unsigned)(i + 1);
        }
        pos = 624;
    }
    auto next = [&]() -> unsigned {
        if (pos == 624) {
            for (int i = 0; i < 624; i++) {
                unsigned y = (mt[i] & 0x80000000u) | (mt[(i + 1) % 624] & 0x7fffffffu);
                mt[i] = mt[(i + 397) % 624] ^ (y >> 1) ^ ((y & 1u) ? 0x9908b0dfu : 0u);
            }
            pos = 0;
        }
        unsigned y = mt[pos++];
        y ^= y >> 11;
        y ^= (y << 7) & 0x9d2c5680u;
        y ^= (y << 15) & 0xefc60000u;
        y ^= y >> 18;
        return y;
    };
    auto nextDouble = [&]() -> double {
        unsigned a = next() >> 5, b = next() >> 6;
        return ((double)a * 67108864.0 + (double)b) / 9007199254740992.0;
    };
    bool has_g = false;
    double gcache = 0.0;
    for (int i = 0; i < DD; i++) {
        double val;
        if (has_g) { val = gcache; has_g = false; }
        else {
            double x1, x2, r2;
            do {
                x1 = 2.0 * nextDouble() - 1.0;
                x2 = 2.0 * nextDouble() - 1.0;
                r2 = x1 * x1 + x2 * x2;
            } while (r2 >= 1.0 || r2 == 0.0);
            double f = sqrt(-2.0 * log(r2) / r2);
            gcache = f * x1; has_g = true; val = f * x2;
        }
        out[i] = (float)val;
    }
}

/* ============================== launcher ================================= */
extern "C" void kernel_launch(void* const* d_in, const int* in_sizes, int n_in,
                              void* d_out, int out_size) {
    const float* x    = (const float*)d_in[0];
    const float* z    = (const float*)d_in[1];
    const float* h0   = (const float*)d_in[2];
    const float* Wx   = (const float*)d_in[3];
    const float* Wh   = (const float*)d_in[4];
    const float* Wg   = (const float*)d_in[5];
    const float* bias = (const float*)d_in[6];

    float* out   = (float*)d_out;
    float* outs  = out;                          /* [T, B, D]   */
    float* out_h = out + (size_t)NROW * DD;      /* [T+1, B, D] */
    const float* hs = out_h + BD;                /* h[1..T], row = t*B+b */

    static float u_host[DD];
    host_randn1024(u_host);
    P1024 u0;
    for (int i = 0; i < DD; i++) u0.v[i] = u_host[i];

    /* launch order fixed so ncu (-s 5 -c 1) captures the scan kernel */
    spectral_kernel<<<1, 1024>>>(Wh, u0);                                     /* 0 */
    init_kernel<<<16, 1024>>>(h0, out_h);                                     /* 1 */
    gemm_kernel<0><<<dim3(128, 8), 256>>>(x, Wx, nullptr, bias,
                                          nullptr, nullptr, 0);               /* 2 */
    gemm_kernel<0><<<dim3(128, 8), 256>>>(x, Wx, nullptr, bias,
                                          nullptr, nullptr, 16384);           /* 3 */
    reset_kernel<<<1, 32>>>();                                                /* 4 */
    scan_kernel<<<SNB, 256>>>(Wh, out_h);                                     /* 5 */
    gemm_kernel<1><<<dim3(256, 8), 256>>>(hs, Wg, outs, nullptr,
                                          z, hs, 0);                          /* 6 */
}